// round 1
// baseline (speedup 1.0000x reference)
#include <cuda_runtime.h>
#include <math.h>

#define HW   400
#define LCH  9
#define BS   2
#define CD   1024
#define CH   256
#define NLB  18          // L*B batches
#define TEMP 20.0f

// ---------------- scratch (device globals; no runtime allocation) ----------------
__device__ float g_sumsq[2 * NLB * HW];
__device__ float g_invn [2 * NLB * HW];
__device__ float g_corr [(size_t)NLB * HW * HW];
__device__ float g_corrt[(size_t)NLB * HW * HW];
__device__ float g_buf1 [(size_t)BS * 10 * HW * HW];
__device__ float g_buf2 [(size_t)BS * 10 * HW * HW];
__device__ float g_c4a  [BS * HW * HW];
__device__ float g_c4b  [BS * HW * HW];
__device__ float g_c4   [BS * HW * HW];
__device__ float g_attn [BS * HW * HW];
__device__ float g_nrm  [2 * BS * HW];

// ---------------- utility ----------------
__global__ void zero_k(float* p, int n) {
    int i = blockIdx.x * blockDim.x + threadIdx.x;
    if (i < n) p[i] = 0.f;
}

// Sum of squares along C (1024) for fq_feats / fs_feats.
// grid (18, 16, 2), block 400. y selects a 64-channel chunk, z selects tensor.
__global__ void sumsq_k(const float* __restrict__ fq, const float* __restrict__ fs,
                        float* __restrict__ out) {
    int z  = blockIdx.z;
    int lb = blockIdx.x;
    int c0 = blockIdx.y * 64;
    int pos = threadIdx.x;              // 0..399
    const float* x = (z ? fs : fq) + ((size_t)lb * CD + c0) * HW + pos;
    float s = 0.f;
    #pragma unroll 8
    for (int c = 0; c < 64; c++) {
        float v = x[(size_t)c * HW];
        s += v * v;
    }
    atomicAdd(&out[z * NLB * HW + lb * HW + pos], s);
}

__global__ void invn_k(const float* __restrict__ s, float* __restrict__ inv, int n) {
    int i = blockIdx.x * blockDim.x + threadIdx.x;
    if (i < n) inv[i] = 1.f / fmaxf(sqrtf(s[i]), 1e-12f);
}

// ---------------- correlation GEMM (TN): corr[b,l,ij,km] = invq*invs* sum_c A[c,ij]*B[c,km]
// grid (7, 7, 18), block 256. Tile 64x64x16, 4x4 per thread.
__global__ void corr_gemm_k(const float* __restrict__ fq, const float* __restrict__ fs,
                            const float* __restrict__ invn, float* __restrict__ corr) {
    int lb = blockIdx.z;                             // l*BS + b (input memory order)
    const float* A  = fq + (size_t)lb * CD * HW;     // [1024][400]
    const float* Bm = fs + (size_t)lb * CD * HW;
    int ij0 = blockIdx.y * 64, km0 = blockIdx.x * 64;

    __shared__ float As[16][64];
    __shared__ float Bsm[16][64];
    int tid = threadIdx.x;
    int tx = tid & 15, ty = tid >> 4;
    float acc[4][4] = {};

    for (int c0 = 0; c0 < CD; c0 += 16) {
        #pragma unroll
        for (int t = tid; t < 1024; t += 256) {
            int kk = t >> 6, col = t & 63;
            int ij = ij0 + col, km = km0 + col;
            As [kk][col] = (ij < HW) ? A [(size_t)(c0 + kk) * HW + ij] : 0.f;
            Bsm[kk][col] = (km < HW) ? Bm[(size_t)(c0 + kk) * HW + km] : 0.f;
        }
        __syncthreads();
        #pragma unroll
        for (int kk = 0; kk < 16; kk++) {
            float a[4], b[4];
            #pragma unroll
            for (int r = 0; r < 4; r++) { a[r] = As[kk][ty * 4 + r]; b[r] = Bsm[kk][tx * 4 + r]; }
            #pragma unroll
            for (int r = 0; r < 4; r++)
                #pragma unroll
                for (int s = 0; s < 4; s++) acc[r][s] += a[r] * b[s];
        }
        __syncthreads();
    }

    int b = lb & 1, l = lb >> 1;
    const float* iq = invn + (size_t)lb * HW;                 // fq norms
    const float* is = invn + NLB * HW + (size_t)lb * HW;      // fs norms
    float* cp = corr + (size_t)(b * LCH + l) * HW * HW;       // corr layout [b][l][ij][km]
    #pragma unroll
    for (int r = 0; r < 4; r++) {
        int ij = ij0 + ty * 4 + r;
        if (ij >= HW) continue;
        float sq = iq[ij];
        #pragma unroll
        for (int s = 0; s < 4; s++) {
            int km = km0 + tx * 4 + s;
            if (km < HW) cp[(size_t)ij * HW + km] = acc[r][s] * sq * is[km];
        }
    }
}

// ---------------- 4D conv layer (3x3x3x3, pad 1 all dims, relu) ----------------
// grid (B*400), block 416. One block per (b,i,j); thread t<400 owns output (k,m).
template <int CIN, int COUT>
__global__ void conv4d_k(const float* __restrict__ x, const float* __restrict__ wt,
                         float* __restrict__ y) {
    __shared__ float ws[CIN * 81 * COUT];
    __shared__ float sp[22 * 22];

    int bij = blockIdx.x;
    int b = bij / HW, ij = bij % HW;
    int i = ij / 20, j = ij % 20;
    int tid = threadIdx.x;

    // weights: global [co][ci][di][dj][dk][dm] -> smem [(ci*81 + plane*9 + tap)*COUT + co]
    for (int t = tid; t < CIN * 81 * COUT; t += blockDim.x) {
        int co = t / (CIN * 81);
        int rem = t - co * (CIN * 81);
        ws[rem * COUT + co] = wt[t];
    }

    float acc[COUT];
    #pragma unroll
    for (int co = 0; co < COUT; co++) acc[co] = 0.f;
    int k = tid / 20, m = tid % 20;
    bool active = tid < HW;

    for (int ci = 0; ci < CIN; ci++) {
        #pragma unroll
        for (int di = 0; di < 3; di++) {
            int ii = i + di - 1;
            #pragma unroll
            for (int dj = 0; dj < 3; dj++) {
                int jj = j + dj - 1;
                __syncthreads();
                bool inb = ((unsigned)ii < 20u) && ((unsigned)jj < 20u);
                const float* src = x + (((size_t)(b * CIN + ci) * 20 + ii) * 20 + jj) * HW;
                for (int t = tid; t < 484; t += blockDim.x) {
                    int kk = t / 22 - 1, mm = t % 22 - 1;
                    float v = 0.f;
                    if (inb && (unsigned)kk < 20u && (unsigned)mm < 20u) v = src[kk * 20 + mm];
                    sp[t] = v;
                }
                __syncthreads();
                if (active) {
                    const float* wp = &ws[(ci * 81 + (di * 3 + dj) * 9) * COUT];
                    float sv[9];
                    #pragma unroll
                    for (int dk = 0; dk < 3; dk++)
                        #pragma unroll
                        for (int dm = 0; dm < 3; dm++)
                            sv[dk * 3 + dm] = sp[(k + dk) * 22 + (m + dm)];
                    #pragma unroll
                    for (int u = 0; u < 9; u++) {
                        float s = sv[u];
                        #pragma unroll
                        for (int co = 0; co < COUT; co++)
                            acc[co] += s * wp[u * COUT + co];
                    }
                }
            }
        }
    }
    if (active) {
        #pragma unroll
        for (int co = 0; co < COUT; co++)
            y[(((size_t)(b * COUT + co) * 20 + i) * 20 + j) * HW + tid] = fmaxf(acc[co], 0.f);
    }
}

// ---------------- tiled transpose of NLB 400x400 matrices ----------------
__global__ void transpose_k(const float* __restrict__ in, float* __restrict__ out) {
    __shared__ float t[32][33];
    int mtx = blockIdx.z;
    const float* A = in  + (size_t)mtx * HW * HW;
    float*       O = out + (size_t)mtx * HW * HW;
    int x0 = blockIdx.x * 32, y0 = blockIdx.y * 32;
    int tx = threadIdx.x, ty = threadIdx.y;
    #pragma unroll
    for (int r = 0; r < 32; r += 8) {
        int yy = y0 + ty + r, xx = x0 + tx;
        t[ty + r][tx] = (yy < HW && xx < HW) ? A[(size_t)yy * HW + xx] : 0.f;
    }
    __syncthreads();
    #pragma unroll
    for (int r = 0; r < 32; r += 8) {
        int yy = x0 + ty + r, xx = y0 + tx;
        if (yy < HW && xx < HW) O[(size_t)yy * HW + xx] = t[tx][ty + r];
    }
}

// c4[b][q][s] = a[b][q][s] + bt[b][s][q]
__global__ void addt_k(const float* __restrict__ a, const float* __restrict__ bt,
                       float* __restrict__ o) {
    __shared__ float t[32][33];
    int b = blockIdx.z;
    const float* A  = a  + (size_t)b * HW * HW;
    const float* Bt = bt + (size_t)b * HW * HW;
    float*       O  = o  + (size_t)b * HW * HW;
    int q0 = blockIdx.y * 32, s0 = blockIdx.x * 32;
    int tx = threadIdx.x, ty = threadIdx.y;
    #pragma unroll
    for (int r = 0; r < 32; r += 8) {
        int s = s0 + ty + r, q = q0 + tx;
        t[ty + r][tx] = (s < HW && q < HW) ? Bt[(size_t)s * HW + q] : 0.f;
    }
    __syncthreads();
    #pragma unroll
    for (int r = 0; r < 32; r += 8) {
        int q = q0 + ty + r, s = s0 + tx;
        if (q < HW && s < HW) O[(size_t)q * HW + s] = A[(size_t)q * HW + s] + t[tx][ty + r];
    }
}

// ---------------- softmax over rows of c4*TEMP ----------------
__global__ void softmax_k(const float* __restrict__ x, float* __restrict__ y) {
    int row = blockIdx.x;
    const float* xr = x + (size_t)row * HW;
    float*       yr = y + (size_t)row * HW;
    __shared__ float sh[HW];
    __shared__ float red[4];
    int tid = threadIdx.x;                       // 128
    float mx = -3.4e38f;
    for (int i = tid; i < HW; i += 128) {
        float v = xr[i] * TEMP;
        sh[i] = v;
        mx = fmaxf(mx, v);
    }
    #pragma unroll
    for (int o = 16; o; o >>= 1) mx = fmaxf(mx, __shfl_xor_sync(0xffffffffu, mx, o));
    if ((tid & 31) == 0) red[tid >> 5] = mx;
    __syncthreads();
    mx = fmaxf(fmaxf(red[0], red[1]), fmaxf(red[2], red[3]));
    float sum = 0.f;
    for (int i = tid; i < HW; i += 128) {
        float e = expf(sh[i] - mx);
        sh[i] = e;
        sum += e;
    }
    #pragma unroll
    for (int o = 16; o; o >>= 1) sum += __shfl_xor_sync(0xffffffffu, sum, o);
    __syncthreads();
    if ((tid & 31) == 0) red[tid >> 5] = sum;
    __syncthreads();
    float inv = 1.f / (red[0] + red[1] + red[2] + red[3]);
    for (int i = tid; i < HW; i += 128) yr[i] = sh[i] * inv;
}

// ---------------- attention GEMM (NT): out[b][c][q] = sum_s v[c][s] * attn[q][s]
// grid (7, 4, 2), block 256. Tile 64x64x16.
__global__ void attn_gemm_k(const float* __restrict__ attn, const float* __restrict__ v,
                            float* __restrict__ out) {
    int b = blockIdx.z;
    const float* A = v    + (size_t)b * CH * HW;     // [256][400]
    const float* P = attn + (size_t)b * HW * HW;     // [400][400]
    int c0 = blockIdx.y * 64, q0 = blockIdx.x * 64;

    __shared__ float As[16][65];
    __shared__ float Ps[16][65];
    int tid = threadIdx.x;
    int tx = tid & 15, ty = tid >> 4;
    float acc[4][4] = {};

    for (int s0 = 0; s0 < HW; s0 += 16) {
        #pragma unroll
        for (int t = tid; t < 1024; t += 256) {
            int row = t >> 4, kk = t & 15;
            int c = c0 + row, q = q0 + row;
            As[kk][row] = (c < CH) ? A[(size_t)c * HW + s0 + kk] : 0.f;
            Ps[kk][row] = (q < HW) ? P[(size_t)q * HW + s0 + kk] : 0.f;
        }
        __syncthreads();
        #pragma unroll
        for (int kk = 0; kk < 16; kk++) {
            float a[4], p[4];
            #pragma unroll
            for (int r = 0; r < 4; r++) { a[r] = As[kk][ty * 4 + r]; p[r] = Ps[kk][tx * 4 + r]; }
            #pragma unroll
            for (int r = 0; r < 4; r++)
                #pragma unroll
                for (int s = 0; s < 4; s++) acc[r][s] += a[r] * p[s];
        }
        __syncthreads();
    }
    #pragma unroll
    for (int r = 0; r < 4; r++) {
        int c = c0 + ty * 4 + r;
        if (c >= CH) continue;
        #pragma unroll
        for (int s = 0; s < 4; s++) {
            int q = q0 + tx * 4 + s;
            if (q < HW) out[((size_t)b * CH + c) * HW + q] = acc[r][s];
        }
    }
}

// ---------------- final norms + combine ----------------
// grid (BS, 2), block 400. z: 0 -> f_q, 1 -> att_fq. Norm over CH=256.
__global__ void norm2_k(const float* __restrict__ fqin, const float* __restrict__ att,
                        float* __restrict__ nrm) {
    int b = blockIdx.x, z = blockIdx.y;
    const float* x = (z ? att : fqin) + (size_t)b * CH * HW + threadIdx.x;
    float s = 0.f;
    #pragma unroll 8
    for (int c = 0; c < CH; c++) {
        float v = x[(size_t)c * HW];
        s += v * v;
    }
    nrm[(z * BS + b) * HW + threadIdx.x] = 1.f / fmaxf(sqrtf(s), 1e-12f);
}

__global__ void combine_k(const float* __restrict__ fqin, const float* __restrict__ att,
                          const float* __restrict__ nrm, float* __restrict__ out) {
    int idx = blockIdx.x * blockDim.x + threadIdx.x;
    if (idx >= BS * CH * HW) return;
    int b = idx / (CH * HW);
    int pos = idx % HW;
    out[idx] = fqin[idx] * nrm[b * HW + pos] + att[idx] * nrm[(BS + b) * HW + pos] * 0.5f;
}

// ---------------- launch ----------------
extern "C" void kernel_launch(void* const* d_in, const int* in_sizes, int n_in,
                              void* d_out, int out_size) {
    const float* fqf = (const float*)d_in[0];
    const float* fsf = (const float*)d_in[1];
    const float* f_q = (const float*)d_in[2];
    const float* f_s = (const float*)d_in[3];
    const float* w1  = (const float*)d_in[4];
    const float* w2  = (const float*)d_in[5];
    const float* w3  = (const float*)d_in[6];
    float* out = (float*)d_out;

    float *sumsq, *invn, *corr, *corrt, *buf1, *buf2, *c4a, *c4b, *c4, *attn, *nrm;
    cudaGetSymbolAddress((void**)&sumsq, g_sumsq);
    cudaGetSymbolAddress((void**)&invn,  g_invn);
    cudaGetSymbolAddress((void**)&corr,  g_corr);
    cudaGetSymbolAddress((void**)&corrt, g_corrt);
    cudaGetSymbolAddress((void**)&buf1,  g_buf1);
    cudaGetSymbolAddress((void**)&buf2,  g_buf2);
    cudaGetSymbolAddress((void**)&c4a,   g_c4a);
    cudaGetSymbolAddress((void**)&c4b,   g_c4b);
    cudaGetSymbolAddress((void**)&c4,    g_c4);
    cudaGetSymbolAddress((void**)&attn,  g_attn);
    cudaGetSymbolAddress((void**)&nrm,   g_nrm);

    const int NSUM = 2 * NLB * HW;

    // 1. feature L2 norms (folded into GEMM epilogue via inverse norms)
    zero_k<<<(NSUM + 255) / 256, 256>>>(sumsq, NSUM);
    sumsq_k<<<dim3(NLB, 16, 2), 400>>>(fqf, fsf, sumsq);
    invn_k<<<(NSUM + 255) / 256, 256>>>(sumsq, invn, NSUM);

    // 2. correlation tensor
    corr_gemm_k<<<dim3(7, 7, NLB), 256>>>(fqf, fsf, invn, corr);

    // 3. neighborhood consensus — branch A
    conv4d_k<9, 10><<<BS * HW, 416>>>(corr, w1, buf1);
    conv4d_k<10, 10><<<BS * HW, 416>>>(buf1, w2, buf2);
    conv4d_k<10, 1><<<BS * HW, 416>>>(buf2, w3, c4a);

    // 4. branch B on transposed correlations
    transpose_k<<<dim3(13, 13, NLB), dim3(32, 8)>>>(corr, corrt);
    conv4d_k<9, 10><<<BS * HW, 416>>>(corrt, w1, buf1);
    conv4d_k<10, 10><<<BS * HW, 416>>>(buf1, w2, buf2);
    conv4d_k<10, 1><<<BS * HW, 416>>>(buf2, w3, c4b);

    // 5. combine branches (B transposed back)
    addt_k<<<dim3(13, 13, BS), dim3(32, 8)>>>(c4a, c4b, c4);

    // 6. softmax + attention
    softmax_k<<<BS * HW, 128>>>(c4, attn);
    attn_gemm_k<<<dim3(7, 4, BS), 256>>>(attn, f_s, out + BS * CH * HW);

    // 7. final L2-norm combine
    norm2_k<<<dim3(BS, 2), 400>>>(f_q, out + BS * CH * HW, nrm);
    combine_k<<<(BS * CH * HW + 255) / 256, 256>>>(f_q, out + BS * CH * HW, nrm, out);
}

// round 2
// speedup vs baseline: 1.0624x; 1.0624x over previous
#include <cuda_runtime.h>
#include <math.h>

#define HW   400
#define LCH  9
#define BS   2
#define CD   1024
#define CH   256
#define NLB  18          // L*B batches
#define TEMP 20.0f

// ---------------- scratch (device globals; no runtime allocation) ----------------
__device__ float g_sumsq[2 * NLB * HW];
__device__ float g_invn [2 * NLB * HW];
__device__ float g_corr [(size_t)NLB * HW * HW];
__device__ float g_corrt[(size_t)NLB * HW * HW];
__device__ float g_buf1 [(size_t)BS * 10 * HW * HW];
__device__ float g_buf2 [(size_t)BS * 10 * HW * HW];
__device__ float g_c4a  [BS * HW * HW];
__device__ float g_c4b  [BS * HW * HW];
__device__ float g_c4   [BS * HW * HW];
__device__ float g_attn [BS * HW * HW];
__device__ float g_nrm  [2 * BS * HW];

// ---------------- utility ----------------
__global__ void zero_k(float* p, int n) {
    int i = blockIdx.x * blockDim.x + threadIdx.x;
    if (i < n) p[i] = 0.f;
}

__global__ void sumsq_k(const float* __restrict__ fq, const float* __restrict__ fs,
                        float* __restrict__ out) {
    int z  = blockIdx.z;
    int lb = blockIdx.x;
    int c0 = blockIdx.y * 64;
    int pos = threadIdx.x;
    const float* x = (z ? fs : fq) + ((size_t)lb * CD + c0) * HW + pos;
    float s = 0.f;
    #pragma unroll 8
    for (int c = 0; c < 64; c++) {
        float v = x[(size_t)c * HW];
        s += v * v;
    }
    atomicAdd(&out[z * NLB * HW + lb * HW + pos], s);
}

__global__ void invn_k(const float* __restrict__ s, float* __restrict__ inv, int n) {
    int i = blockIdx.x * blockDim.x + threadIdx.x;
    if (i < n) inv[i] = 1.f / fmaxf(sqrtf(s[i]), 1e-12f);
}

// ---------------- correlation GEMM (TN) ----------------
// grid (4, 4, 18), block 400. Tile 100x100, K-tile 32, 5x5 strided microtile.
__global__ void __launch_bounds__(400) corr_gemm_k(
        const float* __restrict__ fq, const float* __restrict__ fs,
        const float* __restrict__ invn, float* __restrict__ corr) {
    int lb = blockIdx.z;
    const float* A  = fq + (size_t)lb * CD * HW;
    const float* Bm = fs + (size_t)lb * CD * HW;
    int ij0 = blockIdx.y * 100, km0 = blockIdx.x * 100;

    __shared__ float As[32][100];
    __shared__ float Bsm[32][100];
    int tid = threadIdx.x;
    int tx = tid % 20, ty = tid / 20;
    float acc[5][5] = {};

    for (int c0 = 0; c0 < CD; c0 += 32) {
        #pragma unroll
        for (int it = 0; it < 8; it++) {
            int t = tid + it * 400;
            int kk = t / 100, col = t % 100;
            As [kk][col] = A [(size_t)(c0 + kk) * HW + ij0 + col];
            Bsm[kk][col] = Bm[(size_t)(c0 + kk) * HW + km0 + col];
        }
        __syncthreads();
        #pragma unroll
        for (int kk = 0; kk < 32; kk++) {
            float a[5], b[5];
            #pragma unroll
            for (int r = 0; r < 5; r++) { a[r] = As[kk][r * 20 + ty]; b[r] = Bsm[kk][r * 20 + tx]; }
            #pragma unroll
            for (int r = 0; r < 5; r++)
                #pragma unroll
                for (int s = 0; s < 5; s++) acc[r][s] += a[r] * b[s];
        }
        __syncthreads();
    }

    int b = lb & 1, l = lb >> 1;
    const float* iq = invn + (size_t)lb * HW;
    const float* is = invn + NLB * HW + (size_t)lb * HW;
    float* cp = corr + (size_t)(b * LCH + l) * HW * HW;
    #pragma unroll
    for (int r = 0; r < 5; r++) {
        int ij = ij0 + r * 20 + ty;
        float sq = iq[ij];
        #pragma unroll
        for (int s = 0; s < 5; s++) {
            int km = km0 + s * 20 + tx;
            cp[(size_t)ij * HW + km] = acc[r][s] * sq * is[km];
        }
    }
}

// ---------------- 4D conv layer (3x3x3x3, pad 1, relu) ----------------
// Block per (b,i,j). Thread = (co group g, PKxPM output patch).
// Input patch cached in registers, reused across 9 (dk,dm) taps.
// Per-ci weights staged in smem (broadcast loads).
template <int CIN, int COUT, int PK, int PM>
__global__ void conv4d_k(const float* __restrict__ x, const float* __restrict__ wt,
                         float* __restrict__ y) {
    constexpr int NPATCH   = 400 / (PK * PM);
    constexpr int NTHREADS = NPATCH * COUT;
    constexpr int NPM      = 20 / PM;

    __shared__ float sp[9 * 484];          // 9 padded 22x22 (k,m) planes for current ci
    __shared__ float wc[81 * COUT];        // weights for current ci: [dij*9+tap][co]

    int bij = blockIdx.x;
    int b = bij / HW, ij = bij % HW;
    int i = ij / 20, j = ij % 20;
    int tid = threadIdx.x;
    int g   = tid / NPATCH;                // co
    int pid = tid % NPATCH;
    int k0 = (pid / NPM) * PK;
    int m0 = (pid % NPM) * PM;

    // zero pad ring once (interiors overwritten every ci; pads stay 0)
    for (int t = tid; t < 9 * 484; t += NTHREADS) sp[t] = 0.f;

    float acc[PK][PM];
    #pragma unroll
    for (int pk = 0; pk < PK; pk++)
        #pragma unroll
        for (int pm = 0; pm < PM; pm++) acc[pk][pm] = 0.f;

    for (int ci = 0; ci < CIN; ci++) {
        __syncthreads();
        // stage weights for this ci: wc[dijtap*COUT + co] = wt[co][ci][dijtap]
        for (int t = tid; t < 81 * COUT; t += NTHREADS) {
            int dijtap = t / COUT, co = t % COUT;
            wc[t] = wt[((size_t)co * CIN + ci) * 81 + dijtap];
        }
        // stage 9 neighbor (k,m) planes (interior 20x20 of padded 22x22)
        for (int t = tid; t < 9 * 400; t += NTHREADS) {
            int p = t / 400, rem = t % 400;
            int di = p / 3, dj = p % 3;
            int ii = i + di - 1, jj = j + dj - 1;
            bool v = ((unsigned)ii < 20u) && ((unsigned)jj < 20u);
            float val = v ? x[((size_t)(b * CIN + ci) * 400 + ii * 20 + jj) * 400 + rem] : 0.f;
            int r = rem / 20, c = rem % 20;
            sp[p * 484 + (r + 1) * 22 + (c + 1)] = val;
        }
        __syncthreads();

        for (int dij = 0; dij < 9; dij++) {
            const float* P = sp + dij * 484 + k0 * 22 + m0;
            float xin[PK + 2][PM + 2];
            #pragma unroll
            for (int r = 0; r < PK + 2; r++)
                #pragma unroll
                for (int c = 0; c < PM + 2; c++) xin[r][c] = P[r * 22 + c];

            const float* wp = wc + dij * 9 * COUT + g;
            #pragma unroll
            for (int dk = 0; dk < 3; dk++)
                #pragma unroll
                for (int dm = 0; dm < 3; dm++) {
                    float w = wp[(dk * 3 + dm) * COUT];
                    #pragma unroll
                    for (int pk = 0; pk < PK; pk++)
                        #pragma unroll
                        for (int pm = 0; pm < PM; pm++)
                            acc[pk][pm] += xin[pk + dk][pm + dm] * w;
                }
        }
    }

    float* yp = y + ((size_t)(b * COUT + g) * 400 + ij) * 400;
    #pragma unroll
    for (int pk = 0; pk < PK; pk++)
        #pragma unroll
        for (int pm = 0; pm < PM; pm++)
            yp[(k0 + pk) * 20 + (m0 + pm)] = fmaxf(acc[pk][pm], 0.f);
}

// ---------------- tiled transpose of NLB 400x400 matrices ----------------
__global__ void transpose_k(const float* __restrict__ in, float* __restrict__ out) {
    __shared__ float t[32][33];
    int mtx = blockIdx.z;
    const float* A = in  + (size_t)mtx * HW * HW;
    float*       O = out + (size_t)mtx * HW * HW;
    int x0 = blockIdx.x * 32, y0 = blockIdx.y * 32;
    int tx = threadIdx.x, ty = threadIdx.y;
    #pragma unroll
    for (int r = 0; r < 32; r += 8) {
        int yy = y0 + ty + r, xx = x0 + tx;
        t[ty + r][tx] = (yy < HW && xx < HW) ? A[(size_t)yy * HW + xx] : 0.f;
    }
    __syncthreads();
    #pragma unroll
    for (int r = 0; r < 32; r += 8) {
        int yy = x0 + ty + r, xx = y0 + tx;
        if (yy < HW && xx < HW) O[(size_t)yy * HW + xx] = t[tx][ty + r];
    }
}

// c4[b][q][s] = a[b][q][s] + bt[b][s][q]
__global__ void addt_k(const float* __restrict__ a, const float* __restrict__ bt,
                       float* __restrict__ o) {
    __shared__ float t[32][33];
    int b = blockIdx.z;
    const float* A  = a  + (size_t)b * HW * HW;
    const float* Bt = bt + (size_t)b * HW * HW;
    float*       O  = o  + (size_t)b * HW * HW;
    int q0 = blockIdx.y * 32, s0 = blockIdx.x * 32;
    int tx = threadIdx.x, ty = threadIdx.y;
    #pragma unroll
    for (int r = 0; r < 32; r += 8) {
        int s = s0 + ty + r, q = q0 + tx;
        t[ty + r][tx] = (s < HW && q < HW) ? Bt[(size_t)s * HW + q] : 0.f;
    }
    __syncthreads();
    #pragma unroll
    for (int r = 0; r < 32; r += 8) {
        int q = q0 + ty + r, s = s0 + tx;
        if (q < HW && s < HW) O[(size_t)q * HW + s] = A[(size_t)q * HW + s] + t[tx][ty + r];
    }
}

// ---------------- softmax over rows of c4*TEMP ----------------
__global__ void softmax_k(const float* __restrict__ x, float* __restrict__ y) {
    int row = blockIdx.x;
    const float* xr = x + (size_t)row * HW;
    float*       yr = y + (size_t)row * HW;
    __shared__ float sh[HW];
    __shared__ float red[4];
    int tid = threadIdx.x;
    float mx = -3.4e38f;
    for (int i = tid; i < HW; i += 128) {
        float v = xr[i] * TEMP;
        sh[i] = v;
        mx = fmaxf(mx, v);
    }
    #pragma unroll
    for (int o = 16; o; o >>= 1) mx = fmaxf(mx, __shfl_xor_sync(0xffffffffu, mx, o));
    if ((tid & 31) == 0) red[tid >> 5] = mx;
    __syncthreads();
    mx = fmaxf(fmaxf(red[0], red[1]), fmaxf(red[2], red[3]));
    float sum = 0.f;
    for (int i = tid; i < HW; i += 128) {
        float e = expf(sh[i] - mx);
        sh[i] = e;
        sum += e;
    }
    #pragma unroll
    for (int o = 16; o; o >>= 1) sum += __shfl_xor_sync(0xffffffffu, sum, o);
    __syncthreads();
    if ((tid & 31) == 0) red[tid >> 5] = sum;
    __syncthreads();
    float inv = 1.f / (red[0] + red[1] + red[2] + red[3]);
    for (int i = tid; i < HW; i += 128) yr[i] = sh[i] * inv;
}

// ---------------- attention GEMM (NT): out[b][c][q] = sum_s v[c][s] * attn[q][s]
__global__ void attn_gemm_k(const float* __restrict__ attn, const float* __restrict__ v,
                            float* __restrict__ out) {
    int b = blockIdx.z;
    const float* A = v    + (size_t)b * CH * HW;
    const float* P = attn + (size_t)b * HW * HW;
    int c0 = blockIdx.y * 64, q0 = blockIdx.x * 64;

    __shared__ float As[16][65];
    __shared__ float Ps[16][65];
    int tid = threadIdx.x;
    int tx = tid & 15, ty = tid >> 4;
    float acc[4][4] = {};

    for (int s0 = 0; s0 < HW; s0 += 16) {
        #pragma unroll
        for (int t = tid; t < 1024; t += 256) {
            int row = t >> 4, kk = t & 15;
            int c = c0 + row, q = q0 + row;
            As[kk][row] = (c < CH) ? A[(size_t)c * HW + s0 + kk] : 0.f;
            Ps[kk][row] = (q < HW) ? P[(size_t)q * HW + s0 + kk] : 0.f;
        }
        __syncthreads();
        #pragma unroll
        for (int kk = 0; kk < 16; kk++) {
            float a[4], p[4];
            #pragma unroll
            for (int r = 0; r < 4; r++) { a[r] = As[kk][ty * 4 + r]; p[r] = Ps[kk][tx * 4 + r]; }
            #pragma unroll
            for (int r = 0; r < 4; r++)
                #pragma unroll
                for (int s = 0; s < 4; s++) acc[r][s] += a[r] * p[s];
        }
        __syncthreads();
    }
    #pragma unroll
    for (int r = 0; r < 4; r++) {
        int c = c0 + ty * 4 + r;
        if (c >= CH) continue;
        #pragma unroll
        for (int s = 0; s < 4; s++) {
            int q = q0 + tx * 4 + s;
            if (q < HW) out[((size_t)b * CH + c) * HW + q] = acc[r][s];
        }
    }
}

// ---------------- final norms + combine ----------------
__global__ void norm2_k(const float* __restrict__ fqin, const float* __restrict__ att,
                        float* __restrict__ nrm) {
    int b = blockIdx.x, z = blockIdx.y;
    const float* x = (z ? att : fqin) + (size_t)b * CH * HW + threadIdx.x;
    float s = 0.f;
    #pragma unroll 8
    for (int c = 0; c < CH; c++) {
        float v = x[(size_t)c * HW];
        s += v * v;
    }
    nrm[(z * BS + b) * HW + threadIdx.x] = 1.f / fmaxf(sqrtf(s), 1e-12f);
}

__global__ void combine_k(const float* __restrict__ fqin, const float* __restrict__ att,
                          const float* __restrict__ nrm, float* __restrict__ out) {
    int idx = blockIdx.x * blockDim.x + threadIdx.x;
    if (idx >= BS * CH * HW) return;
    int b = idx / (CH * HW);
    int pos = idx % HW;
    out[idx] = fqin[idx] * nrm[b * HW + pos] + att[idx] * nrm[(BS + b) * HW + pos] * 0.5f;
}

// ---------------- launch ----------------
extern "C" void kernel_launch(void* const* d_in, const int* in_sizes, int n_in,
                              void* d_out, int out_size) {
    const float* fqf = (const float*)d_in[0];
    const float* fsf = (const float*)d_in[1];
    const float* f_q = (const float*)d_in[2];
    const float* f_s = (const float*)d_in[3];
    const float* w1  = (const float*)d_in[4];
    const float* w2  = (const float*)d_in[5];
    const float* w3  = (const float*)d_in[6];
    float* out = (float*)d_out;

    float *sumsq, *invn, *corr, *corrt, *buf1, *buf2, *c4a, *c4b, *c4, *attn, *nrm;
    cudaGetSymbolAddress((void**)&sumsq, g_sumsq);
    cudaGetSymbolAddress((void**)&invn,  g_invn);
    cudaGetSymbolAddress((void**)&corr,  g_corr);
    cudaGetSymbolAddress((void**)&corrt, g_corrt);
    cudaGetSymbolAddress((void**)&buf1,  g_buf1);
    cudaGetSymbolAddress((void**)&buf2,  g_buf2);
    cudaGetSymbolAddress((void**)&c4a,   g_c4a);
    cudaGetSymbolAddress((void**)&c4b,   g_c4b);
    cudaGetSymbolAddress((void**)&c4,    g_c4);
    cudaGetSymbolAddress((void**)&attn,  g_attn);
    cudaGetSymbolAddress((void**)&nrm,   g_nrm);

    const int NSUM = 2 * NLB * HW;

    // 1. feature L2 norms (folded into GEMM epilogue via inverse norms)
    zero_k<<<(NSUM + 255) / 256, 256>>>(sumsq, NSUM);
    sumsq_k<<<dim3(NLB, 16, 2), 400>>>(fqf, fsf, sumsq);
    invn_k<<<(NSUM + 255) / 256, 256>>>(sumsq, invn, NSUM);

    // 2. correlation tensor
    corr_gemm_k<<<dim3(4, 4, NLB), 400>>>(fqf, fsf, invn, corr);

    // 3. neighborhood consensus — branch A
    conv4d_k<9, 10, 5, 5><<<BS * HW, 160>>>(corr, w1, buf1);
    conv4d_k<10, 10, 5, 5><<<BS * HW, 160>>>(buf1, w2, buf2);
    conv4d_k<10, 1, 5, 1><<<BS * HW, 80>>>(buf2, w3, c4a);

    // 4. branch B on transposed correlations
    transpose_k<<<dim3(13, 13, NLB), dim3(32, 8)>>>(corr, corrt);
    conv4d_k<9, 10, 5, 5><<<BS * HW, 160>>>(corrt, w1, buf1);
    conv4d_k<10, 10, 5, 5><<<BS * HW, 160>>>(buf1, w2, buf2);
    conv4d_k<10, 1, 5, 1><<<BS * HW, 80>>>(buf2, w3, c4b);

    // 5. combine branches (B transposed back)
    addt_k<<<dim3(13, 13, BS), dim3(32, 8)>>>(c4a, c4b, c4);

    // 6. softmax + attention
    softmax_k<<<BS * HW, 128>>>(c4, attn);
    attn_gemm_k<<<dim3(7, 4, BS), 256>>>(attn, f_s, out + BS * CH * HW);

    // 7. final L2-norm combine
    norm2_k<<<dim3(BS, 2), 400>>>(f_q, out + BS * CH * HW, nrm);
    combine_k<<<(BS * CH * HW + 255) / 256, 256>>>(f_q, out + BS * CH * HW, nrm, out);
}